// round 14
// baseline (speedup 1.0000x reference)
#include <cuda_runtime.h>
#include <cstdint>
#include <math.h>

#define Hh 96
#define Ww 96
#define Bn 4
#define Cc 64
#define HW (Hh*Ww)
#define KK 9
#define CIN2 130
#define PBLK 128           // pixels per deform block
#define NPAIRH 33          // cin-pairs per conv half
#define NST2 17            // conv pipeline stages (2 pairs each)

// Scratch (device globals)
__device__ float g_fjt[Bn*HW*Cc];      // frame_j as [B,HW,C]
__device__ float g_w2[KK*16*64*4];     // w_reg as [tap][chquad][o][e]
__device__ float g_wc2[66*28*20];      // conv w: [cinpair][oc(28)][tap(10)][c(2)]
__device__ float g_part[8*28*HW];      // conv partials [b*2+half][28][HW]

// ---------------------------------------------------------------------------
__device__ __forceinline__ void cpa4(unsigned int dst, const void* src, bool pred) {
    int sz = pred ? 4 : 0;
    asm volatile("cp.async.ca.shared.global [%0], [%1], 4, %2;\n"
                 :: "r"(dst), "l"(src), "r"(sz));
}
__device__ __forceinline__ void cpa_commit() {
    asm volatile("cp.async.commit_group;\n");
}
__device__ __forceinline__ unsigned long long ffma2(
    unsigned long long a, unsigned long long b, unsigned long long c) {
    unsigned long long d;
    asm("fma.rn.f32x2 %0, %1, %2, %3;" : "=l"(d) : "l"(a), "l"(b), "l"(c));
    return d;
}
__device__ __forceinline__ float2 unpack2(unsigned long long v) {
    float lo, hi;
    asm("mov.b64 {%0, %1}, %2;" : "=f"(lo), "=f"(hi) : "l"(v));
    return make_float2(lo, hi);
}

// ---------------------------------------------------------------------------
// frame_j [B,C,H,W] -> [B,HW,C]
// ---------------------------------------------------------------------------
__global__ void k_transpose(const float* __restrict__ fj) {
    __shared__ float s[64][33];
    int b   = blockIdx.y;
    int hw0 = blockIdx.x * 32;
    int tid = threadIdx.x;
    int tx = tid & 31, ty = tid >> 5;
#pragma unroll
    for (int i = 0; i < 8; i++) {
        int c = ty + i * 8;
        s[c][tx] = fj[(size_t)(b * Cc + c) * HW + hw0 + tx];
    }
    __syncthreads();
    int ci = tid & 63, j4 = tid >> 6;
#pragma unroll
    for (int i = 0; i < 8; i++) {
        int j = j4 + i * 4;
        g_fjt[(size_t)(b * HW + hw0 + j) * Cc + ci] = s[ci][j];
    }
}

// ---------------------------------------------------------------------------
// Fused weight prep
// ---------------------------------------------------------------------------
__global__ void k_wprep(const float* __restrict__ w_reg,
                        const float* __restrict__ w_off,
                        const float* __restrict__ w_mod) {
    int i = blockIdx.x * 256 + threadIdx.x;
    if (i < KK * 4096) {
        int tap = i >> 12;
        int r   = i & 4095;
        int q   = r >> 8;
        int r2  = r & 255;
        int o   = r2 >> 2;
        int e   = r2 & 3;
        g_w2[i] = w_reg[(o * 64 + q * 4 + e) * KK + tap];
    } else if (i < KK * 4096 + 66 * 560) {
        int j = i - KK * 4096;
        int pr = j / 560;
        int r  = j % 560;
        int oc = r / 20;
        int r2 = r % 20;
        int tap = r2 >> 1, c = r2 & 1;
        int cin = 2 * pr + c;
        float v = 0.f;
        if (tap < 9 && oc < 27 && cin < CIN2)
            v = (oc < 18) ? w_off[(oc * CIN2 + cin) * 9 + tap]
                          : w_mod[((oc - 18) * CIN2 + cin) * 9 + tap];
        g_wc2[j] = v;
    }
}

// ---------------------------------------------------------------------------
// Fused 3x3 conv (half the cin reduction per block). Channel-pair FFMA2.
// ---------------------------------------------------------------------------
__global__ void __launch_bounds__(256, 2) k_conv(
    const float* __restrict__ fi, const float* __restrict__ fj,
    const float* __restrict__ fl)
{
    __shared__ __align__(16) float s_in[3][2][680];
    __shared__ __align__(16) float s_w[3][2][560];
    int z  = blockIdx.z;
    int b  = z >> 1, half = z & 1;
    int pr_base = half * NPAIRH;
    int x0 = blockIdx.x * 32, y0 = blockIdx.y * 8;
    int tid = threadIdx.x;
    int tx   = tid & 31;
    int warp = tid >> 5;
    int ocg  = warp >> 1;
    int wrow = (warp & 1) * 4;
    int obase = ocg * 7;

    int ily0 = tid / 34,  ilx0 = tid % 34;
    int i1   = tid + 256;
    int ily1 = i1 / 34,   ilx1 = i1 % 34;
    int gy0 = y0 + ily0 - 1, gx0 = x0 + ilx0 - 1;
    int gy1 = y0 + ily1 - 1, gx1 = x0 + ilx1 - 1;
    bool sok0 = (gy0 >= 0 && gy0 < Hh && gx0 >= 0 && gx0 < Ww);
    bool sok1 = (tid < 84) && (gy1 >= 0 && gy1 < Hh && gx1 >= 0 && gx1 < Ww);
    int soff0 = sok0 ? (gy0 * Ww + gx0) : 0;
    int soff1 = sok1 ? (gy1 * Ww + gx1) : 0;

    auto stage = [&](int s, int buf) {
#pragma unroll
        for (int pp = 0; pp < 2; pp++) {
            int lc = 2 * s + pp;
            bool okp = (lc < NPAIRH);
            int pr = pr_base + (okp ? lc : 0);
#pragma unroll
            for (int c = 0; c < 2; c++) {
                int cin = 2 * pr + c;
                bool vc = okp && (cin < CIN2);
                int ci2 = vc ? cin : 128;
                const float* src = (ci2 < 64)  ? fi + (size_t)(b * 64 + ci2) * HW
                                 : (ci2 < 128) ? fj + (size_t)(b * 64 + ci2 - 64) * HW
                                               : fl + (size_t)(b * 2 + ci2 - 128) * HW;
                float* din = s_in[buf][pp];
                cpa4((unsigned int)__cvta_generic_to_shared(din + tid * 2 + c),
                     src + soff0, vc && sok0);
                if (tid < 84)
                    cpa4((unsigned int)__cvta_generic_to_shared(din + (tid + 256) * 2 + c),
                         src + soff1, vc && sok1);
            }
            const float* wsrc = g_wc2 + (size_t)pr * 560;
            float* dw = s_w[buf][pp];
            cpa4((unsigned int)__cvta_generic_to_shared(dw + tid), wsrc + tid, okp);
            cpa4((unsigned int)__cvta_generic_to_shared(dw + tid + 256),
                 wsrc + tid + 256, okp);
            if (tid < 48)
                cpa4((unsigned int)__cvta_generic_to_shared(dw + tid + 512),
                     wsrc + tid + 512, okp);
        }
    };

    unsigned long long acc2[7][4];
#pragma unroll
    for (int oi = 0; oi < 7; oi++)
#pragma unroll
        for (int px = 0; px < 4; px++) acc2[oi][px] = 0ull;

    stage(0, 0); cpa_commit();
    stage(1, 1); cpa_commit();

    for (int s = 0; s < NST2; s++) {
        if (s < NST2 - 1) asm volatile("cp.async.wait_group 1;\n");
        else              asm volatile("cp.async.wait_group 0;\n");
        __syncthreads();
        int buf = s % 3;
#pragma unroll
        for (int pp = 0; pp < 2; pp++) {
            const float* sb = s_in[buf][pp] + (wrow * 34 + tx) * 2;
            unsigned long long t2[6][3];
#pragma unroll
            for (int jr = 0; jr < 6; jr++)
#pragma unroll
                for (int jc = 0; jc < 3; jc++)
                    t2[jr][jc] = *(const unsigned long long*)(sb + (jr * 34 + jc) * 2);

            const float* swb = s_w[buf][pp];
#pragma unroll
            for (int oi = 0; oi < 7; oi++) {
                const float* wr = swb + (obase + oi) * 20;
                ulonglong2 wA = *(const ulonglong2*)wr;
                ulonglong2 wB = *(const ulonglong2*)(wr + 4);
                ulonglong2 wC = *(const ulonglong2*)(wr + 8);
                ulonglong2 wD = *(const ulonglong2*)(wr + 12);
                unsigned long long w8 = *(const unsigned long long*)(wr + 16);
#pragma unroll
                for (int px = 0; px < 4; px++) {
                    unsigned long long a = acc2[oi][px];
                    a = ffma2(t2[px + 0][0], wA.x, a);
                    a = ffma2(t2[px + 0][1], wA.y, a);
                    a = ffma2(t2[px + 0][2], wB.x, a);
                    a = ffma2(t2[px + 1][0], wB.y, a);
                    a = ffma2(t2[px + 1][1], wC.x, a);
                    a = ffma2(t2[px + 1][2], wC.y, a);
                    a = ffma2(t2[px + 2][0], wD.x, a);
                    a = ffma2(t2[px + 2][1], wD.y, a);
                    a = ffma2(t2[px + 2][2], w8, a);
                    acc2[oi][px] = a;
                }
            }
        }
        if (s + 2 < NST2) { stage(s + 2, (s + 2) % 3); cpa_commit(); }
    }

#pragma unroll
    for (int oi = 0; oi < 7; oi++) {
        float* dst = g_part + ((size_t)z * 28 + obase + oi) * HW;
#pragma unroll
        for (int px = 0; px < 4; px++) {
            float2 u = unpack2(acc2[oi][px]);
            dst[(y0 + wrow + px) * Ww + x0 + tx] = u.x + u.y;
        }
    }
}

// ---------------------------------------------------------------------------
// Deformable conv v2: block = 128 pixels x 64 outputs, 256 threads.
// 4 pixels x 8 ocs per thread (32 packed accumulators). s_v XOR-swizzled
// (no padding). Bilinear coefficients recomputed in-gather (no s_cw/s_ci).
// ---------------------------------------------------------------------------
__global__ void __launch_bounds__(256, 2) k_deform(
    float* __restrict__ out,
    const float* __restrict__ b_off, const float* __restrict__ b_mod)
{
    __shared__ __align__(16) float s_v[PBLK * 64];   // 32768 B, swizzled
    __shared__ __align__(16) float s_w[4096];        // 16384 B   (total 48 KB)

    int b   = blockIdx.y;
    int p0  = blockIdx.x * PBLK;
    int tid = threadIdx.x;

    const float* P0 = g_part + (size_t)(b * 2)     * 28 * HW;
    const float* P1 = g_part + (size_t)(b * 2 + 1) * 28 * HW;
    const float* fb = g_fjt + (size_t)b * HW * Cc;

    // gather mapping: 2 threads per pixel (8 quads each)
    int gp  = tid >> 1;                 // pixel 0..127
    int hq  = (tid & 1) * 8;            // quad base
    int gpp = p0 + gp;
    int gy  = gpp / Ww, gx = gpp % Ww;
    int gsw = gp & 15;                  // swizzle key for this pixel

    // contract mapping
    int lane = tid & 31;
    int o0   = (tid >> 5) * 8;
    int lsw  = lane & 15;

    unsigned long long a2[32];
#pragma unroll
    for (int oi = 0; oi < 32; oi++) a2[oi] = 0ull;

    for (int tap = 0; tap < 9; tap++) {
        // stage weight tap tile [16 q][64 o][4 e] -> s_w
        {
            const float4* src = (const float4*)(g_w2 + tap * 4096);
            float4* dst = (float4*)s_w;
#pragma unroll
            for (int i = 0; i < 4; i++)
                dst[tid + i * 256] = src[tid + i * 256];
        }
        // gather: compute bilinear coefficients, then 8 quads
        {
            float offy = P0[(2 * tap)     * HW + gpp] + P1[(2 * tap)     * HW + gpp]
                       + b_off[2 * tap];
            float offx = P0[(2 * tap + 1) * HW + gpp] + P1[(2 * tap + 1) * HW + gpp]
                       + b_off[2 * tap + 1];
            float zz   = P0[(18 + tap)    * HW + gpp] + P1[(18 + tap)    * HW + gpp]
                       + b_mod[tap];
            float m = 2.f / (1.f + expf(-zz));
            int ky = tap / 3, kx = tap % 3;
            float py = (float)(gy - 1 + ky) + offy;
            float px = (float)(gx - 1 + kx) + offx;
            float fy = floorf(py), fx = floorf(px);
            int y0i = (int)fy, x0i = (int)fx;
            float wy = py - fy, wx = px - fx;
            float cw[4];
            int   ci[4];
#pragma unroll
            for (int d = 0; d < 4; d++) {
                int dy = d >> 1, dx = d & 1;
                int yc = y0i + dy, xc = x0i + dx;
                bool ok = (yc >= 0) && (yc < Hh) && (xc >= 0) && (xc < Ww);
                float w = (dy ? wy : 1.f - wy) * (dx ? wx : 1.f - wx) * m;
                cw[d] = ok ? w : 0.f;
                int ycc = min(max(yc, 0), Hh - 1);
                int xcc = min(max(xc, 0), Ww - 1);
                ci[d] = ycc * Ww + xcc;
            }
            const float* pp0 = fb + (size_t)ci[0] * Cc;
            const float* pp1 = fb + (size_t)ci[1] * Cc;
            const float* pp2 = fb + (size_t)ci[2] * Cc;
            const float* pp3 = fb + (size_t)ci[3] * Cc;
            float w0 = cw[0], w1 = cw[1], w2 = cw[2], w3 = cw[3];
            float* svrow = s_v + gp * 64;
#pragma unroll
            for (int k = 0; k < 8; k++) {
                int q  = hq + k;
                int qe = q ^ gsw;
                float4 f0 = *(const float4*)(pp0 + q * 4);
                float4 f1 = *(const float4*)(pp1 + q * 4);
                float4 f2 = *(const float4*)(pp2 + q * 4);
                float4 f3 = *(const float4*)(pp3 + q * 4);
                float4 v;
                v.x = w0 * f0.x + w1 * f1.x + w2 * f2.x + w3 * f3.x;
                v.y = w0 * f0.y + w1 * f1.y + w2 * f2.y + w3 * f3.y;
                v.z = w0 * f0.z + w1 * f1.z + w2 * f2.z + w3 * f3.z;
                v.w = w0 * f0.w + w1 * f1.w + w2 * f2.w + w3 * f3.w;
                *(float4*)(svrow + qe * 4) = v;
            }
        }
        __syncthreads();

        // contract: 4 pixels x 8 outputs per thread
        {
            const float* va = s_v + (lane)      * 64;
            const float* vb = s_v + (lane + 32) * 64;
            const float* vc = s_v + (lane + 64) * 64;
            const float* vd = s_v + (lane + 96) * 64;
#pragma unroll 4
            for (int q = 0; q < 16; q++) {
                int qe4 = (q ^ lsw) * 4;
                ulonglong2 ta = *(const ulonglong2*)(va + qe4);
                ulonglong2 tb = *(const ulonglong2*)(vb + qe4);
                ulonglong2 tc = *(const ulonglong2*)(vc + qe4);
                ulonglong2 td = *(const ulonglong2*)(vd + qe4);
                const float* wq = s_w + (q * 64 + o0) * 4;
#pragma unroll
                for (int oi = 0; oi < 8; oi++) {
                    ulonglong2 wv = *(const ulonglong2*)(wq + oi * 4);
                    unsigned long long x0 = a2[oi];
                    x0 = ffma2(ta.x, wv.x, x0);
                    x0 = ffma2(ta.y, wv.y, x0);
                    a2[oi] = x0;
                    unsigned long long x1 = a2[8 + oi];
                    x1 = ffma2(tb.x, wv.x, x1);
                    x1 = ffma2(tb.y, wv.y, x1);
                    a2[8 + oi] = x1;
                    unsigned long long x2 = a2[16 + oi];
                    x2 = ffma2(tc.x, wv.x, x2);
                    x2 = ffma2(tc.y, wv.y, x2);
                    a2[16 + oi] = x2;
                    unsigned long long x3 = a2[24 + oi];
                    x3 = ffma2(td.x, wv.x, x3);
                    x3 = ffma2(td.y, wv.y, x3);
                    a2[24 + oi] = x3;
                }
            }
        }
        __syncthreads();
    }

#pragma unroll
    for (int oi = 0; oi < 8; oi++) {
        size_t base = (size_t)(b * 64 + o0 + oi) * HW + p0;
        float2 u0 = unpack2(a2[oi]);
        float2 u1 = unpack2(a2[8 + oi]);
        float2 u2 = unpack2(a2[16 + oi]);
        float2 u3 = unpack2(a2[24 + oi]);
        out[base + lane]      = u0.x + u0.y;
        out[base + 32 + lane] = u1.x + u1.y;
        out[base + 64 + lane] = u2.x + u2.y;
        out[base + 96 + lane] = u3.x + u3.y;
    }
}

// ---------------------------------------------------------------------------
extern "C" void kernel_launch(void* const* d_in, const int* in_sizes, int n_in,
                              void* d_out, int out_size) {
    const float* frame_i = (const float*)d_in[0];
    const float* frame_j = (const float*)d_in[1];
    const float* flow_ij = (const float*)d_in[2];
    const float* w_off   = (const float*)d_in[3];
    const float* b_off   = (const float*)d_in[4];
    const float* w_mod   = (const float*)d_in[5];
    const float* b_mod   = (const float*)d_in[6];
    const float* w_reg   = (const float*)d_in[7];
    float* out = (float*)d_out;

    k_transpose<<<dim3(HW / 32, Bn), 256>>>(frame_j);
    k_wprep<<<(KK * 4096 + 66 * 560 + 255) / 256, 256>>>(w_reg, w_off, w_mod);
    k_conv<<<dim3(Ww / 32, Hh / 8, Bn * 2), 256>>>(frame_i, frame_j, flow_ij);
    k_deform<<<dim3(HW / PBLK, Bn), 256>>>(out, b_off, b_mod);
}

// round 15
// speedup vs baseline: 1.2511x; 1.2511x over previous
#include <cuda_runtime.h>
#include <cstdint>
#include <math.h>

#define Hh 96
#define Ww 96
#define Bn 4
#define Cc 64
#define HW (Hh*Ww)
#define KK 9
#define CIN2 130
#define PBLK 64            // pixels per deform block
#define VPITCH 68          // s_v row pitch (bank pad)
#define NPAIRH 33          // cin-pairs per conv half
#define NST2 17            // conv pipeline stages (2 pairs each)
#define DEF_SMEM (2*PBLK*VPITCH*4 + 2*4096*4 + PBLK*9*4*4 + PBLK*9*4*2)

// Scratch (device globals)
__device__ float g_fjt[Bn*HW*Cc];      // frame_j as [B,HW,C]
__device__ float g_w2[KK*16*64*4];     // w_reg as [tap][chquad][o][e]
__device__ float g_wc2[66*28*20];      // conv w: [cinpair][oc(28)][tap(10)][c(2)]
__device__ float g_part[8*28*HW];      // conv partials [b*2+half][28][HW]

// ---------------------------------------------------------------------------
__device__ __forceinline__ void cpa4(unsigned int dst, const void* src, bool pred) {
    int sz = pred ? 4 : 0;
    asm volatile("cp.async.ca.shared.global [%0], [%1], 4, %2;\n"
                 :: "r"(dst), "l"(src), "r"(sz));
}
__device__ __forceinline__ void cpa_commit() {
    asm volatile("cp.async.commit_group;\n");
}
__device__ __forceinline__ unsigned long long ffma2(
    unsigned long long a, unsigned long long b, unsigned long long c) {
    unsigned long long d;
    asm("fma.rn.f32x2 %0, %1, %2, %3;" : "=l"(d) : "l"(a), "l"(b), "l"(c));
    return d;
}
__device__ __forceinline__ float2 unpack2(unsigned long long v) {
    float lo, hi;
    asm("mov.b64 {%0, %1}, %2;" : "=f"(lo), "=f"(hi) : "l"(v));
    return make_float2(lo, hi);
}

// ---------------------------------------------------------------------------
// frame_j [B,C,H,W] -> [B,HW,C]
// ---------------------------------------------------------------------------
__global__ void k_transpose(const float* __restrict__ fj) {
    __shared__ float s[64][33];
    int b   = blockIdx.y;
    int hw0 = blockIdx.x * 32;
    int tid = threadIdx.x;
    int tx = tid & 31, ty = tid >> 5;
#pragma unroll
    for (int i = 0; i < 8; i++) {
        int c = ty + i * 8;
        s[c][tx] = fj[(size_t)(b * Cc + c) * HW + hw0 + tx];
    }
    __syncthreads();
    int ci = tid & 63, j4 = tid >> 6;
#pragma unroll
    for (int i = 0; i < 8; i++) {
        int j = j4 + i * 4;
        g_fjt[(size_t)(b * HW + hw0 + j) * Cc + ci] = s[ci][j];
    }
}

// ---------------------------------------------------------------------------
// Fused weight prep
// ---------------------------------------------------------------------------
__global__ void k_wprep(const float* __restrict__ w_reg,
                        const float* __restrict__ w_off,
                        const float* __restrict__ w_mod) {
    int i = blockIdx.x * 256 + threadIdx.x;
    if (i < KK * 4096) {
        int tap = i >> 12;
        int r   = i & 4095;
        int q   = r >> 8;
        int r2  = r & 255;
        int o   = r2 >> 2;
        int e   = r2 & 3;
        g_w2[i] = w_reg[(o * 64 + q * 4 + e) * KK + tap];
    } else if (i < KK * 4096 + 66 * 560) {
        int j = i - KK * 4096;
        int pr = j / 560;
        int r  = j % 560;
        int oc = r / 20;
        int r2 = r % 20;
        int tap = r2 >> 1, c = r2 & 1;
        int cin = 2 * pr + c;
        float v = 0.f;
        if (tap < 9 && oc < 27 && cin < CIN2)
            v = (oc < 18) ? w_off[(oc * CIN2 + cin) * 9 + tap]
                          : w_mod[((oc - 18) * CIN2 + cin) * 9 + tap];
        g_wc2[j] = v;
    }
}

// ---------------------------------------------------------------------------
// Fused 3x3 conv (half the cin reduction per block). Channel-pair FFMA2.
// ---------------------------------------------------------------------------
__global__ void __launch_bounds__(256, 2) k_conv(
    const float* __restrict__ fi, const float* __restrict__ fj,
    const float* __restrict__ fl)
{
    __shared__ __align__(16) float s_in[3][2][680];
    __shared__ __align__(16) float s_w[3][2][560];
    int z  = blockIdx.z;
    int b  = z >> 1, half = z & 1;
    int pr_base = half * NPAIRH;
    int x0 = blockIdx.x * 32, y0 = blockIdx.y * 8;
    int tid = threadIdx.x;
    int tx   = tid & 31;
    int warp = tid >> 5;
    int ocg  = warp >> 1;
    int wrow = (warp & 1) * 4;
    int obase = ocg * 7;

    int ily0 = tid / 34,  ilx0 = tid % 34;
    int i1   = tid + 256;
    int ily1 = i1 / 34,   ilx1 = i1 % 34;
    int gy0 = y0 + ily0 - 1, gx0 = x0 + ilx0 - 1;
    int gy1 = y0 + ily1 - 1, gx1 = x0 + ilx1 - 1;
    bool sok0 = (gy0 >= 0 && gy0 < Hh && gx0 >= 0 && gx0 < Ww);
    bool sok1 = (tid < 84) && (gy1 >= 0 && gy1 < Hh && gx1 >= 0 && gx1 < Ww);
    int soff0 = sok0 ? (gy0 * Ww + gx0) : 0;
    int soff1 = sok1 ? (gy1 * Ww + gx1) : 0;

    auto stage = [&](int s, int buf) {
#pragma unroll
        for (int pp = 0; pp < 2; pp++) {
            int lc = 2 * s + pp;
            bool okp = (lc < NPAIRH);
            int pr = pr_base + (okp ? lc : 0);
#pragma unroll
            for (int c = 0; c < 2; c++) {
                int cin = 2 * pr + c;
                bool vc = okp && (cin < CIN2);
                int ci2 = vc ? cin : 128;
                const float* src = (ci2 < 64)  ? fi + (size_t)(b * 64 + ci2) * HW
                                 : (ci2 < 128) ? fj + (size_t)(b * 64 + ci2 - 64) * HW
                                               : fl + (size_t)(b * 2 + ci2 - 128) * HW;
                float* din = s_in[buf][pp];
                cpa4((unsigned int)__cvta_generic_to_shared(din + tid * 2 + c),
                     src + soff0, vc && sok0);
                if (tid < 84)
                    cpa4((unsigned int)__cvta_generic_to_shared(din + (tid + 256) * 2 + c),
                         src + soff1, vc && sok1);
            }
            const float* wsrc = g_wc2 + (size_t)pr * 560;
            float* dw = s_w[buf][pp];
            cpa4((unsigned int)__cvta_generic_to_shared(dw + tid), wsrc + tid, okp);
            cpa4((unsigned int)__cvta_generic_to_shared(dw + tid + 256),
                 wsrc + tid + 256, okp);
            if (tid < 48)
                cpa4((unsigned int)__cvta_generic_to_shared(dw + tid + 512),
                     wsrc + tid + 512, okp);
        }
    };

    unsigned long long acc2[7][4];
#pragma unroll
    for (int oi = 0; oi < 7; oi++)
#pragma unroll
        for (int px = 0; px < 4; px++) acc2[oi][px] = 0ull;

    stage(0, 0); cpa_commit();
    stage(1, 1); cpa_commit();

    for (int s = 0; s < NST2; s++) {
        if (s < NST2 - 1) asm volatile("cp.async.wait_group 1;\n");
        else              asm volatile("cp.async.wait_group 0;\n");
        __syncthreads();
        int buf = s % 3;
#pragma unroll
        for (int pp = 0; pp < 2; pp++) {
            const float* sb = s_in[buf][pp] + (wrow * 34 + tx) * 2;
            unsigned long long t2[6][3];
#pragma unroll
            for (int jr = 0; jr < 6; jr++)
#pragma unroll
                for (int jc = 0; jc < 3; jc++)
                    t2[jr][jc] = *(const unsigned long long*)(sb + (jr * 34 + jc) * 2);

            const float* swb = s_w[buf][pp];
#pragma unroll
            for (int oi = 0; oi < 7; oi++) {
                const float* wr = swb + (obase + oi) * 20;
                ulonglong2 wA = *(const ulonglong2*)wr;
                ulonglong2 wB = *(const ulonglong2*)(wr + 4);
                ulonglong2 wC = *(const ulonglong2*)(wr + 8);
                ulonglong2 wD = *(const ulonglong2*)(wr + 12);
                unsigned long long w8 = *(const unsigned long long*)(wr + 16);
#pragma unroll
                for (int px = 0; px < 4; px++) {
                    unsigned long long a = acc2[oi][px];
                    a = ffma2(t2[px + 0][0], wA.x, a);
                    a = ffma2(t2[px + 0][1], wA.y, a);
                    a = ffma2(t2[px + 0][2], wB.x, a);
                    a = ffma2(t2[px + 1][0], wB.y, a);
                    a = ffma2(t2[px + 1][1], wC.x, a);
                    a = ffma2(t2[px + 1][2], wC.y, a);
                    a = ffma2(t2[px + 2][0], wD.x, a);
                    a = ffma2(t2[px + 2][1], wD.y, a);
                    a = ffma2(t2[px + 2][2], w8, a);
                    acc2[oi][px] = a;
                }
            }
        }
        if (s + 2 < NST2) { stage(s + 2, (s + 2) % 3); cpa_commit(); }
    }

#pragma unroll
    for (int oi = 0; oi < 7; oi++) {
        float* dst = g_part + ((size_t)z * 28 + obase + oi) * HW;
#pragma unroll
        for (int px = 0; px < 4; px++) {
            float2 u = unpack2(acc2[oi][px]);
            dst[(y0 + wrow + px) * Ww + x0 + tx] = u.x + u.y;
        }
    }
}

// ---------------------------------------------------------------------------
// Deformable conv: block = 64 pixels x 64 outputs, 256 threads.
// R11 contract shape, but s_v AND s_w double-buffered (dynamic smem):
// gather/wstage for tap t+1 overlap contract of tap t; ONE barrier per tap.
// ---------------------------------------------------------------------------
__global__ void __launch_bounds__(256, 2) k_deform(
    float* __restrict__ out,
    const float* __restrict__ b_off, const float* __restrict__ b_mod)
{
    extern __shared__ __align__(16) float dsm[];
    float* s_v  = dsm;                                   // 2 * PBLK*VPITCH
    float* s_wb = dsm + 2 * PBLK * VPITCH;               // 2 * 4096
    float* s_cw = s_wb + 2 * 4096;                       // PBLK*9*4
    unsigned short* s_ci = (unsigned short*)(s_cw + PBLK * 9 * 4);

    int b   = blockIdx.y;
    int p0  = blockIdx.x * PBLK;
    int tid = threadIdx.x;

    const float* P0 = g_part + (size_t)(b * 2)     * 28 * HW;
    const float* P1 = g_part + (size_t)(b * 2 + 1) * 28 * HW;

    for (int i = tid; i < PBLK * 9; i += 256) {
        int pix = i / 9, tap = i % 9;
        int p = p0 + pix;
        int y = p / Ww, x = p % Ww;
        int ky = tap / 3, kx = tap % 3;
        float offy = P0[(2 * tap)     * HW + p] + P1[(2 * tap)     * HW + p]
                   + b_off[2 * tap];
        float offx = P0[(2 * tap + 1) * HW + p] + P1[(2 * tap + 1) * HW + p]
                   + b_off[2 * tap + 1];
        float zz   = P0[(18 + tap)    * HW + p] + P1[(18 + tap)    * HW + p]
                   + b_mod[tap];
        float m = 2.f / (1.f + expf(-zz));
        float py = (float)(y - 1 + ky) + offy;
        float px = (float)(x - 1 + kx) + offx;
        float fy = floorf(py), fx = floorf(px);
        int y0i = (int)fy, x0i = (int)fx;
        float wy = py - fy, wx = px - fx;
#pragma unroll
        for (int d = 0; d < 4; d++) {
            int dy = d >> 1, dx = d & 1;
            int yc = y0i + dy, xc = x0i + dx;
            bool ok = (yc >= 0) && (yc < Hh) && (xc >= 0) && (xc < Ww);
            float w = (dy ? wy : 1.f - wy) * (dx ? wx : 1.f - wx) * m;
            s_cw[i * 4 + d] = ok ? w : 0.f;
            int ycc = min(max(yc, 0), Hh - 1);
            int xcc = min(max(xc, 0), Ww - 1);
            s_ci[i * 4 + d] = (unsigned short)(ycc * Ww + xcc);
        }
    }

    unsigned long long a2[16];
#pragma unroll
    for (int oi = 0; oi < 16; oi++) a2[oi] = 0ull;

    int lane = tid & 31;
    int o0   = (tid >> 5) * 8;
    int gp   = tid >> 3;
    int gq   = tid & 7;
    const float* fb = g_fjt + (size_t)b * HW * Cc;

    auto wstage = [&](int tap, int buf) {
        const float4* src = (const float4*)(g_w2 + tap * 4096);
        float4* dst = (float4*)(s_wb + buf * 4096);
#pragma unroll
        for (int i = 0; i < 4; i++)
            dst[tid + i * 256] = src[tid + i * 256];
    };

    auto gather = [&](int tap, int buf) {
        float* sv = s_v + buf * PBLK * VPITCH;
#pragma unroll
        for (int ph = 0; ph < 2; ph++) {
            int pix = gp + 32 * ph;
            int j = pix * 9 + tap;
            float w0 = s_cw[j * 4 + 0], w1 = s_cw[j * 4 + 1];
            float w2 = s_cw[j * 4 + 2], w3 = s_cw[j * 4 + 3];
            const float* pp0 = fb + (size_t)s_ci[j * 4 + 0] * Cc;
            const float* pp1 = fb + (size_t)s_ci[j * 4 + 1] * Cc;
            const float* pp2 = fb + (size_t)s_ci[j * 4 + 2] * Cc;
            const float* pp3 = fb + (size_t)s_ci[j * 4 + 3] * Cc;
#pragma unroll
            for (int qq = 0; qq < 2; qq++) {
                int q = gq + qq * 8;
                float4 f0 = *(const float4*)(pp0 + q * 4);
                float4 f1 = *(const float4*)(pp1 + q * 4);
                float4 f2 = *(const float4*)(pp2 + q * 4);
                float4 f3 = *(const float4*)(pp3 + q * 4);
                float4 v;
                v.x = w0 * f0.x + w1 * f1.x + w2 * f2.x + w3 * f3.x;
                v.y = w0 * f0.y + w1 * f1.y + w2 * f2.y + w3 * f3.y;
                v.z = w0 * f0.z + w1 * f1.z + w2 * f2.z + w3 * f3.z;
                v.w = w0 * f0.w + w1 * f1.w + w2 * f2.w + w3 * f3.w;
                *(float4*)(sv + pix * VPITCH + q * 4) = v;
            }
        }
    };

    __syncthreads();            // s_cw/s_ci ready
    wstage(0, 0);
    gather(0, 0);
    __syncthreads();            // buffer 0 ready

    for (int tap = 0; tap < 9; tap++) {
        int buf = tap & 1;
        // prefetch next tap into the other buffer (overlaps contract below)
        if (tap < 8) {
            wstage(tap + 1, buf ^ 1);
            gather(tap + 1, buf ^ 1);
        }
        // contract tap from current buffer
        {
            const float* va = s_v + buf * PBLK * VPITCH + lane * VPITCH;
            const float* vb = va + 32 * VPITCH;
            const float* sw = s_wb + buf * 4096;
#pragma unroll 4
            for (int q = 0; q < 16; q++) {
                ulonglong2 ta = *(const ulonglong2*)(va + q * 4);
                ulonglong2 tb = *(const ulonglong2*)(vb + q * 4);
#pragma unroll
                for (int oi = 0; oi < 8; oi++) {
                    ulonglong2 wv = *(const ulonglong2*)(sw + (q * 64 + o0 + oi) * 4);
                    unsigned long long x = a2[oi];
                    x = ffma2(ta.x, wv.x, x);
                    x = ffma2(ta.y, wv.y, x);
                    a2[oi] = x;
                    unsigned long long y2 = a2[8 + oi];
                    y2 = ffma2(tb.x, wv.x, y2);
                    y2 = ffma2(tb.y, wv.y, y2);
                    a2[8 + oi] = y2;
                }
            }
        }
        __syncthreads();
    }

#pragma unroll
    for (int oi = 0; oi < 8; oi++) {
        size_t base = (size_t)(b * 64 + o0 + oi) * HW + p0;
        float2 ua = unpack2(a2[oi]);
        float2 ub = unpack2(a2[8 + oi]);
        out[base + lane]      = ua.x + ua.y;
        out[base + 32 + lane] = ub.x + ub.y;
    }
}

// ---------------------------------------------------------------------------
extern "C" void kernel_launch(void* const* d_in, const int* in_sizes, int n_in,
                              void* d_out, int out_size) {
    const float* frame_i = (const float*)d_in[0];
    const float* frame_j = (const float*)d_in[1];
    const float* flow_ij = (const float*)d_in[2];
    const float* w_off   = (const float*)d_in[3];
    const float* b_off   = (const float*)d_in[4];
    const float* w_mod   = (const float*)d_in[5];
    const float* b_mod   = (const float*)d_in[6];
    const float* w_reg   = (const float*)d_in[7];
    float* out = (float*)d_out;

    cudaFuncSetAttribute(k_deform, cudaFuncAttributeMaxDynamicSharedMemorySize,
                         DEF_SMEM);

    k_transpose<<<dim3(HW / 32, Bn), 256>>>(frame_j);
    k_wprep<<<(KK * 4096 + 66 * 560 + 255) / 256, 256>>>(w_reg, w_off, w_mod);
    k_conv<<<dim3(Ww / 32, Hh / 8, Bn * 2), 256>>>(frame_i, frame_j, flow_ij);
    k_deform<<<dim3(HW / PBLK, Bn), 256, DEF_SMEM>>>(out, b_off, b_mod);
}